// round 4
// baseline (speedup 1.0000x reference)
#include <cuda_runtime.h>
#include <float.h>

#define BATCH   32
#define HH      2048
#define WW      2048
#define NPB     (HH * WW)              // 4194304 elements per batch
#define CHUNKS  64
#define TPB     256
#define EPC     (NPB / CHUNKS)         // 65536 elements per chunk
#define V4PC    (EPC / 4)              // 16384 float4 per chunk
#define ITERS   (V4PC / TPB)           // 64 iterations per thread
#define K       16

// Scratch (no allocations allowed in kernel_launch)
__device__ float g_cand_v[BATCH * CHUNKS * K];
__device__ int   g_cand_i[BATCH * CHUNKS * K];
__device__ float g_bloss[BATCH];

// Insert (v,id) into register-resident descending-sorted top-K.
// Strict '>' : on equal values the incumbent (earlier = smaller index, since
// each thread scans indices in ascending order) stays above — matches
// jax.lax.top_k's smallest-index-first tie rule.
__device__ __forceinline__ void ins16(float v, int id, float (&tv)[K], int (&ti)[K]) {
#pragma unroll
    for (int j = 0; j < K; ++j) {
        if (v > tv[j]) {
            float fv = tv[j]; tv[j] = v; v = fv;
            int   fi = ti[j]; ti[j] = id; id = fi;
        }
    }
}

// Merge lists [abase..abase+16) and [bbase..bbase+16) (both descending-sorted,
// equal values in ascending index order) into list at abase, keeping top-16.
// Two-pointer over smem (dynamic indices OK in shared), output staged in
// statically-indexed register arrays (no spills). At read time x+y = r <= 15,
// so x,y <= 15: reads always in range, no guards needed.
__device__ __forceinline__ void merge_lists(float* sv, int* si, int abase, int bbase) {
    float rv[K]; int ri[K];
    int x = 0, y = 0;
#pragma unroll
    for (int r = 0; r < K; ++r) {
        float av = sv[abase + x]; int ai = si[abase + x];
        float bv = sv[bbase + y]; int bi = si[bbase + y];
        bool takeA = (av > bv) || (av == bv && ai < bi);
        if (takeA) { rv[r] = av; ri[r] = ai; ++x; }
        else       { rv[r] = bv; ri[r] = bi; ++y; }
    }
#pragma unroll
    for (int r = 0; r < K; ++r) { sv[abase + r] = rv[r]; si[abase + r] = ri[r]; }
}

// Kernel 1: streaming scan + exact per-block top-16 via pairwise merge tree.
__global__ __launch_bounds__(TPB) void topk_scan(const float* __restrict__ in) {
    const int blk   = blockIdx.x;
    const int batch = blk / CHUNKS;
    const int chunk = blk % CHUNKS;
    const int tid   = threadIdx.x;

    const float4* __restrict__ p = reinterpret_cast<const float4*>(
        in + (size_t)batch * NPB + (size_t)chunk * EPC);

    float tv[K];
    int   ti[K];
#pragma unroll
    for (int j = 0; j < K; ++j) { tv[j] = -FLT_MAX; ti[j] = 0x7fffffff; }

    const int idx_base0 = chunk * EPC;

#pragma unroll 4
    for (int it = 0; it < ITERS; ++it) {
        const int v4 = it * TPB + tid;
        float4 q = __ldcs(p + v4);
        float m = fmaxf(fmaxf(q.x, q.y), fmaxf(q.z, q.w));
        if (m > tv[K - 1]) {                       // rare path
            const int base = idx_base0 + (v4 << 2);
            if (q.x > tv[K - 1]) ins16(q.x, base + 0, tv, ti);
            if (q.y > tv[K - 1]) ins16(q.y, base + 1, tv, ti);
            if (q.z > tv[K - 1]) ins16(q.z, base + 2, tv, ti);
            if (q.w > tv[K - 1]) ins16(q.w, base + 3, tv, ti);
        }
    }

    // 256 sorted 16-lists in smem -> pairwise merge tree (8 levels) -> list 0.
    __shared__ float sv[TPB * K];
    __shared__ int   si[TPB * K];
#pragma unroll
    for (int j = 0; j < K; ++j) { sv[tid * K + j] = tv[j]; si[tid * K + j] = ti[j]; }

    for (int s = 1; s < TPB; s <<= 1) {
        __syncthreads();
        const int nmerge = TPB / (s << 1);
        if (tid < nmerge) {
            const int abase = (tid * (s << 1)) * K;
            merge_lists(sv, si, abase, abase + s * K);
        }
    }
    __syncthreads();

    if (tid < K) {
        g_cand_v[blk * K + tid] = sv[tid];
        g_cand_i[blk * K + tid] = si[tid];
    }
}

__device__ __forceinline__ float smooth_l1(float pred, float target) {
    float d  = pred - target;
    float ad = fabsf(d);
    return (ad < 1.0f) ? 0.5f * d * d : ad - 0.5f;
}

// Kernel 2: per-batch merge of 64 sorted chunk lists (6 levels) + loss partial.
__global__ __launch_bounds__(TPB) void topk_final(const float* __restrict__ center_rate) {
    const int batch = blockIdx.x;
    const int tid   = threadIdx.x;
    const int NC    = CHUNKS * K;   // 1024 candidates

    __shared__ float sv[CHUNKS * K];
    __shared__ int   si[CHUNKS * K];
    for (int j = tid; j < NC; j += TPB) {
        sv[j] = g_cand_v[batch * NC + j];
        si[j] = g_cand_i[batch * NC + j];
    }

    for (int s = 1; s < CHUNKS; s <<= 1) {
        __syncthreads();
        const int nmerge = CHUNKS / (s << 1);
        if (tid < nmerge) {
            const int abase = (tid * (s << 1)) * K;
            merge_lists(sv, si, abase, abase + s * K);
        }
    }
    __syncthreads();

    if (tid < K) {
        const int id = si[tid];
        const float rr = (float)(id / WW);
        const float cc = (float)(id % WW);
        const float p0 = rr / (float)(HH - 1);
        const float p1 = cc / (float)(WW - 1);
        const float t0 = center_rate[batch * 2 + 0];
        const float t1 = center_rate[batch * 2 + 1];
        float l = smooth_l1(p0, t0) + smooth_l1(p1, t1);
#pragma unroll
        for (int o = 8; o; o >>= 1) l += __shfl_down_sync(0x0000ffffu, l, o);
        if (tid == 0) g_bloss[batch] = l;
    }
}

// Kernel 3: final scalar.
__global__ void finalize(float* __restrict__ out) {
    float l = (threadIdx.x < BATCH) ? g_bloss[threadIdx.x] : 0.0f;
#pragma unroll
    for (int o = 16; o; o >>= 1) l += __shfl_down_sync(0xffffffffu, l, o);
    if (threadIdx.x == 0) out[0] = l * (1.0f / (float)(BATCH * K * 2));
}

extern "C" void kernel_launch(void* const* d_in, const int* in_sizes, int n_in,
                              void* d_out, int out_size) {
    // cls_input is 32*2048*2048 = 33554432 elems; center_rate is 64.
    const float* cls = (const float*)d_in[0];
    const float* cr  = (const float*)d_in[1];
    if (n_in >= 2 && in_sizes[0] < in_sizes[1]) {   // defensive order check
        cls = (const float*)d_in[1];
        cr  = (const float*)d_in[0];
    }
    float* out = (float*)d_out;

    topk_scan<<<BATCH * CHUNKS, TPB>>>(cls);
    topk_final<<<BATCH, TPB>>>(cr);
    finalize<<<1, 32>>>(out);
}

// round 7
// speedup vs baseline: 4.3811x; 4.3811x over previous
#include <cuda_runtime.h>
#include <float.h>

#define BATCH   32
#define HH      2048
#define WW      2048
#define NPB     (HH * WW)              // 4194304 elements per batch
#define CHUNKS  64
#define TPB     256
#define EPC     (NPB / CHUNKS)         // 65536 elements per chunk
#define V4PC    (EPC / 4)              // 16384 float4 per chunk
#define ITERS   (V4PC / TPB)           // 64 float4 per thread
#define K       16
#define CAP     32768                  // candidate capacity per batch
#define THRESH  3.0f                   // P(N(0,1) > 3) ~ 1.35e-3 -> ~5.7K cands/batch

// ---- device scratch (no allocations allowed) ----
__device__ unsigned long long g_cand[(size_t)BATCH * CAP];   // 8 MB
__device__ int                g_cnt[BATCH];
__device__ float              g_bloss[BATCH];

// Monotonic float -> uint mapping (total order preserved).
__device__ __forceinline__ unsigned int fkey(float f) {
    unsigned int b = __float_as_uint(f);
    return b ^ ((unsigned int)(((int)b) >> 31) | 0x80000000u);
}
// Packed comparator key: value desc primary, index asc secondary (jax top_k tie rule).
__device__ __forceinline__ unsigned long long make_key(float v, int idx) {
    return ((unsigned long long)fkey(v) << 32) | (unsigned int)(~idx);
}
__device__ __forceinline__ int key_to_idx(unsigned long long k) {
    return (int)(~(unsigned int)k) & (NPB - 1);
}

// ---------------- kernel 0: zero counters ----------------
__global__ void zero_cnt() {
    if (threadIdx.x < BATCH) g_cnt[threadIdx.x] = 0;
}

// ---------------- kernel 1: streaming threshold scan ----------------
// Mainline per float4: 1 LDG.128 + 3 FMNMX + 1 FSETP + branch. Candidates
// (x > THRESH) are pushed to the per-batch global buffer via one aggregated
// atomic per hit-group; correctness never depends on THRESH (fixup below
// restores exactness if the filter misfires).
__global__ __launch_bounds__(TPB) void topk_scan(const float* __restrict__ in) {
    const int blk   = blockIdx.x;
    const int batch = blk / CHUNKS;
    const int chunk = blk % CHUNKS;
    const int tid   = threadIdx.x;

    const float4* __restrict__ p = reinterpret_cast<const float4*>(
        in + (size_t)batch * NPB + (size_t)chunk * EPC);
    unsigned long long* cand = g_cand + (size_t)batch * CAP;
    const int idx_base0 = chunk * EPC;

#pragma unroll 8
    for (int it = 0; it < ITERS; ++it) {
        const int v4 = it * TPB + tid;
        float4 q = __ldcs(p + v4);
        float m = fmaxf(fmaxf(q.x, q.y), fmaxf(q.z, q.w));
        if (m > THRESH) {                                    // rare (~0.5% of groups)
            const int base = idx_base0 + (v4 << 2);
            unsigned long long kk[4];
            int n = 0;
            if (q.x > THRESH) kk[n++] = make_key(q.x, base + 0);
            if (q.y > THRESH) kk[n++] = make_key(q.y, base + 1);
            if (q.z > THRESH) kk[n++] = make_key(q.z, base + 2);
            if (q.w > THRESH) kk[n++] = make_key(q.w, base + 3);
            int pos = atomicAdd(&g_cnt[batch], n);           // one reservation
            for (int j = 0; j < n; ++j)
                if (pos + j < CAP) cand[pos + j] = kk[j];
        }
    }
}

// ---- exact-fallback helpers (R2-proven merge machinery, on packed keys) ----
__device__ __forceinline__ void ins16k(unsigned long long k, unsigned long long (&tv)[K]) {
#pragma unroll
    for (int j = 0; j < K; ++j) {
        if (k > tv[j]) { unsigned long long f = tv[j]; tv[j] = k; k = f; }
    }
}
__device__ __forceinline__ void merge_lists_k(unsigned long long* sv, int abase, int bbase) {
    unsigned long long rv[K];
    int x = 0, y = 0;
#pragma unroll
    for (int r = 0; r < K; ++r) {
        unsigned long long a = sv[abase + x], b = sv[bbase + y];
        if (a > b) { rv[r] = a; ++x; } else { rv[r] = b; ++y; }
    }
#pragma unroll
    for (int r = 0; r < K; ++r) sv[abase + r] = rv[r];
}

// ---------------- kernel 2: fixup (exactness guarantee) ----------------
// If 16 <= cnt <= CAP the filter provably captured the top-16 (16th value > T)
// and this returns immediately. Otherwise: exact full re-scan of the batch.
__global__ __launch_bounds__(TPB) void fixup(const float* __restrict__ in) {
    const int batch = blockIdx.x;
    const int tid   = threadIdx.x;
    const int cnt   = g_cnt[batch];
    if (cnt >= K && cnt <= CAP) return;        // uniform exit; normal path

    const float* bp = in + (size_t)batch * NPB;
    unsigned long long tv[K];
#pragma unroll
    for (int j = 0; j < K; ++j) tv[j] = 0ull;
    for (int i = tid; i < NPB; i += TPB) {
        unsigned long long k = make_key(bp[i], i);
        if (k > tv[K - 1]) ins16k(k, tv);
    }
    __shared__ unsigned long long sv[TPB * K];  // 32 KB
#pragma unroll
    for (int j = 0; j < K; ++j) sv[tid * K + j] = tv[j];
    for (int s = 1; s < TPB; s <<= 1) {
        __syncthreads();
        if (tid < TPB / (s << 1)) {
            const int abase = (tid * (s << 1)) * K;
            merge_lists_k(sv, abase, abase + s * K);
        }
    }
    __syncthreads();
    if (tid < K) g_cand[(size_t)batch * CAP + tid] = sv[tid];
    if (tid == 0) g_cnt[batch] = K;
}

__device__ __forceinline__ float smooth_l1(float pred, float target) {
    float d  = pred - target;
    float ad = fabsf(d);
    return (ad < 1.0f) ? 0.5f * d * d : ad - 0.5f;
}

// ---------------- kernel 3: exact top-16 of candidates + loss partial ----------------
__global__ __launch_bounds__(TPB) void select_loss(const float* __restrict__ center_rate) {
    const int batch = blockIdx.x;
    const int tid   = threadIdx.x;
    const int lane  = tid & 31, wid = tid >> 5;
    int cnt = g_cnt[batch]; if (cnt > CAP) cnt = CAP;
    const unsigned long long* cand = g_cand + (size_t)batch * CAP;

    __shared__ unsigned long long red[8];
    __shared__ unsigned long long winner;
    __shared__ int widx[K];
    unsigned long long prev = ~0ull;           // select in strictly-decreasing key order

    for (int r = 0; r < K; ++r) {
        unsigned long long best = 0ull;
        for (int j = tid; j < cnt; j += TPB) {
            unsigned long long k = cand[j];
            if (k < prev && k > best) best = k;
        }
#pragma unroll
        for (int o = 16; o; o >>= 1) {
            unsigned long long ov = __shfl_down_sync(0xffffffffu, best, o);
            if (ov > best) best = ov;
        }
        if (lane == 0) red[wid] = best;
        __syncthreads();
        if (tid == 0) {
            unsigned long long b = red[0];
#pragma unroll
            for (int w = 1; w < 8; ++w) if (red[w] > b) b = red[w];
            winner  = b;
            widx[r] = key_to_idx(b);
        }
        __syncthreads();
        prev = winner;
    }

    if (tid < K) {
        const int id = widx[tid];
        const float p0 = (float)(id / WW) * (1.0f / (float)(HH - 1));
        const float p1 = (float)(id % WW) * (1.0f / (float)(WW - 1));
        const float t0 = center_rate[batch * 2 + 0];
        const float t1 = center_rate[batch * 2 + 1];
        float l = smooth_l1(p0, t0) + smooth_l1(p1, t1);
#pragma unroll
        for (int o = 8; o; o >>= 1) l += __shfl_down_sync(0x0000ffffu, l, o);
        if (tid == 0) g_bloss[batch] = l;
    }
}

// ---------------- kernel 4: final scalar ----------------
__global__ void finalize(float* __restrict__ out) {
    float l = (threadIdx.x < BATCH) ? g_bloss[threadIdx.x] : 0.0f;
#pragma unroll
    for (int o = 16; o; o >>= 1) l += __shfl_down_sync(0xffffffffu, l, o);
    if (threadIdx.x == 0) out[0] = l * (1.0f / (float)(BATCH * K * 2));
}

extern "C" void kernel_launch(void* const* d_in, const int* in_sizes, int n_in,
                              void* d_out, int out_size) {
    // cls_input = 33554432 elems; center_rate = 64.
    const float* cls = (const float*)d_in[0];
    const float* cr  = (const float*)d_in[1];
    if (n_in >= 2 && in_sizes[0] < in_sizes[1]) {   // defensive order check
        cls = (const float*)d_in[1];
        cr  = (const float*)d_in[0];
    }
    float* out = (float*)d_out;

    zero_cnt<<<1, 32>>>();
    topk_scan<<<BATCH * CHUNKS, TPB>>>(cls);
    fixup<<<BATCH, TPB>>>(cls);
    select_loss<<<BATCH, TPB>>>(cr);
    finalize<<<1, 32>>>(out);
}

// round 8
// speedup vs baseline: 7.2621x; 1.6576x over previous
#include <cuda_runtime.h>
#include <float.h>

#define BATCH   32
#define HH      2048
#define WW      2048
#define NPB     (HH * WW)              // 4194304 elements per batch
#define CHUNKS  128
#define TPB     256
#define EPC     (NPB / CHUNKS)         // 32768 elements per chunk
#define V4PC    (EPC / 4)              // 8192 float4 per chunk
#define ITERS   (V4PC / TPB)           // 32 float4 per thread
#define K       16
#define RCAP    256                    // per-block candidate region (mean ~7.6 hits, 88 sigma)
#define SELCAP  4096                   // smem select capacity (mean total ~975)
#define THRESH  3.5f                   // P(N(0,1)>3.5) ~ 2.33e-4 -> ~975 cands/batch

// ---- device scratch (no allocations allowed) ----
__device__ unsigned long long g_cand[(size_t)BATCH * CHUNKS * RCAP];  // 8 MB
__device__ int                g_bcnt[BATCH * CHUNKS];
__device__ float              g_bloss[BATCH];

// Monotonic float -> uint mapping (total order preserved).
__device__ __forceinline__ unsigned int fkey(float f) {
    unsigned int b = __float_as_uint(f);
    return b ^ ((unsigned int)(((int)b) >> 31) | 0x80000000u);
}
// Packed key: value desc primary, index asc secondary (jax top_k tie rule).
// Any finite-value key is >= 2^32 > 0, so 0 is a safe "empty" sentinel.
__device__ __forceinline__ unsigned long long make_key(float v, int idx) {
    return ((unsigned long long)fkey(v) << 32) | (unsigned int)(~idx);
}
__device__ __forceinline__ int key_to_idx(unsigned long long k) {
    return (int)(~(unsigned int)k) & (NPB - 1);
}

// ---------------- kernel 1: streaming threshold scan ----------------
// Mainline per float4: LDG.128 + 3 FMNMX + FSETP. Hits buffered via smem
// atomics, dumped coalesced to this block's private region. g_bcnt written
// unconditionally every run (no zeroing kernel, no global atomics).
__global__ __launch_bounds__(TPB) void topk_scan(const float* __restrict__ in) {
    const int blk   = blockIdx.x;
    const int batch = blk / CHUNKS;
    const int chunk = blk % CHUNKS;
    const int tid   = threadIdx.x;

    const float4* __restrict__ p = reinterpret_cast<const float4*>(
        in + (size_t)batch * NPB + (size_t)chunk * EPC);
    const int idx_base0 = chunk * EPC;

    __shared__ unsigned long long sbuf[RCAP];
    __shared__ int scnt;
    if (tid == 0) scnt = 0;
    __syncthreads();

#pragma unroll 8
    for (int it = 0; it < ITERS; ++it) {
        const int v4 = it * TPB + tid;
        float4 q = __ldcs(p + v4);
        float m = fmaxf(fmaxf(q.x, q.y), fmaxf(q.z, q.w));
        if (m > THRESH) {                                    // ~0.09% of groups
            const int base = idx_base0 + (v4 << 2);
            unsigned long long kk[4];
            int n = 0;
            if (q.x > THRESH) kk[n++] = make_key(q.x, base + 0);
            if (q.y > THRESH) kk[n++] = make_key(q.y, base + 1);
            if (q.z > THRESH) kk[n++] = make_key(q.z, base + 2);
            if (q.w > THRESH) kk[n++] = make_key(q.w, base + 3);
            int pos = atomicAdd(&scnt, n);                   // smem atomic
            for (int j = 0; j < n; ++j)
                if (pos + j < RCAP) sbuf[pos + j] = kk[j];
        }
    }
    __syncthreads();

    const int c = scnt;
    unsigned long long* reg = g_cand + (size_t)blk * RCAP;
    for (int i = tid; i < min(c, RCAP); i += TPB) reg[i] = sbuf[i];
    if (tid == 0) g_bcnt[blk] = c;                           // may exceed RCAP -> overflow marker
}

// ---- exact-fallback helpers (R2-proven merge machinery, on packed keys) ----
__device__ __forceinline__ void ins16k(unsigned long long k, unsigned long long (&tv)[K]) {
#pragma unroll
    for (int j = 0; j < K; ++j) {
        if (k > tv[j]) { unsigned long long f = tv[j]; tv[j] = k; k = f; }
    }
}
__device__ __forceinline__ void merge_lists_k(unsigned long long* sv, int abase, int bbase) {
    unsigned long long rv[K];
    int x = 0, y = 0;
#pragma unroll
    for (int r = 0; r < K; ++r) {
        unsigned long long a = sv[abase + x], b = sv[bbase + y];
        if (a > b) { rv[r] = a; ++x; } else { rv[r] = b; ++y; }
    }
#pragma unroll
    for (int r = 0; r < K; ++r) sv[abase + r] = rv[r];
}

// ---------------- kernel 2: fixup (unconditional exactness) ----------------
// Normal case (no region overflow, total >= K): filter provably captured the
// top-16 (16th value > THRESH). Otherwise: exact full re-scan of the batch.
__global__ __launch_bounds__(TPB) void fixup(const float* __restrict__ in) {
    const int batch = blockIdx.x;
    const int tid   = threadIdx.x;

    __shared__ int s_tot, s_bad;
    if (tid == 0) { s_tot = 0; s_bad = 0; }
    __syncthreads();
    if (tid < CHUNKS) {
        int c = g_bcnt[batch * CHUNKS + tid];
        atomicAdd(&s_tot, c);
        if (c > RCAP) atomicOr(&s_bad, 1);
    }
    __syncthreads();
    if (!s_bad && s_tot >= K) return;          // uniform exit; normal path

    // Exact fallback: full batch re-scan with merge tree.
    const float* bp = in + (size_t)batch * NPB;
    unsigned long long tv[K];
#pragma unroll
    for (int j = 0; j < K; ++j) tv[j] = 0ull;
    for (int i = tid; i < NPB; i += TPB) {
        unsigned long long k = make_key(bp[i], i);
        if (k > tv[K - 1]) ins16k(k, tv);
    }
    __shared__ unsigned long long sv[TPB * K];  // 32 KB
#pragma unroll
    for (int j = 0; j < K; ++j) sv[tid * K + j] = tv[j];
    for (int s = 1; s < TPB; s <<= 1) {
        __syncthreads();
        if (tid < TPB / (s << 1)) {
            const int abase = (tid * (s << 1)) * K;
            merge_lists_k(sv, abase, abase + s * K);
        }
    }
    __syncthreads();
    if (tid < K) g_cand[(size_t)(batch * CHUNKS) * RCAP + tid] = sv[tid];
    if (tid < CHUNKS) g_bcnt[batch * CHUNKS + tid] = (tid == 0) ? K : 0;
}

__device__ __forceinline__ float smooth_l1(float pred, float target) {
    float d  = pred - target;
    float ad = fabsf(d);
    return (ad < 1.0f) ? 0.5f * d * d : ad - 0.5f;
}

// ---------------- kernel 3: compact to smem + 16 knockout rounds + loss ----------------
__global__ __launch_bounds__(TPB) void select_loss(const float* __restrict__ center_rate) {
    const int batch = blockIdx.x;
    const int tid   = threadIdx.x;
    const int lane  = tid & 31, wid = tid >> 5;

    __shared__ int cnts[CHUNKS];
    __shared__ int offs[CHUNKS + 1];
    __shared__ unsigned long long sk[SELCAP];   // 32 KB
    __shared__ unsigned long long red[8];
    __shared__ unsigned long long winner;
    __shared__ int widx[K];

    if (tid < CHUNKS) {
        int c = g_bcnt[batch * CHUNKS + tid];
        cnts[tid] = (c > RCAP) ? RCAP : c;
    }
    __syncthreads();
    if (tid == 0) {
        int acc = 0;
        for (int r = 0; r < CHUNKS; ++r) { offs[r] = acc; acc += cnts[r]; }
        offs[CHUNKS] = acc;
    }
    __syncthreads();
    const int total = offs[CHUNKS];
    const bool in_smem = (total <= SELCAP);

    if (in_smem) {
        // Each warp compacts 16 regions.
        for (int r = wid * (CHUNKS / 8); r < (wid + 1) * (CHUNKS / 8); ++r) {
            const int c = cnts[r];
            const unsigned long long* reg = g_cand + (size_t)(batch * CHUNKS + r) * RCAP;
            for (int i = lane; i < c; i += 32) sk[offs[r] + i] = reg[i];
        }
        __syncthreads();
    }

    unsigned long long prev = ~0ull;            // strictly-decreasing key knockout
    for (int r = 0; r < K; ++r) {
        unsigned long long best = 0ull;
        if (in_smem) {
            for (int j = tid; j < total; j += TPB) {
                unsigned long long k = sk[j];
                if (k < prev && k > best) best = k;
            }
        } else {                                // fallback: scan regions in global
            for (int c2 = 0; c2 < CHUNKS; ++c2) {
                const int c = cnts[c2];
                const unsigned long long* reg = g_cand + (size_t)(batch * CHUNKS + c2) * RCAP;
                for (int j = tid; j < c; j += TPB) {
                    unsigned long long k = reg[j];
                    if (k < prev && k > best) best = k;
                }
            }
        }
#pragma unroll
        for (int o = 16; o; o >>= 1) {
            unsigned long long ov = __shfl_down_sync(0xffffffffu, best, o);
            if (ov > best) best = ov;
        }
        if (lane == 0) red[wid] = best;
        __syncthreads();
        if (tid == 0) {
            unsigned long long b = red[0];
#pragma unroll
            for (int w = 1; w < 8; ++w) if (red[w] > b) b = red[w];
            winner  = b;
            widx[r] = key_to_idx(b);
        }
        __syncthreads();
        prev = winner;
    }

    if (tid < K) {
        const int id = widx[tid];
        const float p0 = (float)(id / WW) * (1.0f / (float)(HH - 1));
        const float p1 = (float)(id % WW) * (1.0f / (float)(WW - 1));
        const float t0 = center_rate[batch * 2 + 0];
        const float t1 = center_rate[batch * 2 + 1];
        float l = smooth_l1(p0, t0) + smooth_l1(p1, t1);
#pragma unroll
        for (int o = 8; o; o >>= 1) l += __shfl_down_sync(0x0000ffffu, l, o);
        if (tid == 0) g_bloss[batch] = l;
    }
}

// ---------------- kernel 4: final scalar ----------------
__global__ void finalize(float* __restrict__ out) {
    float l = (threadIdx.x < BATCH) ? g_bloss[threadIdx.x] : 0.0f;
#pragma unroll
    for (int o = 16; o; o >>= 1) l += __shfl_down_sync(0xffffffffu, l, o);
    if (threadIdx.x == 0) out[0] = l * (1.0f / (float)(BATCH * K * 2));
}

extern "C" void kernel_launch(void* const* d_in, const int* in_sizes, int n_in,
                              void* d_out, int out_size) {
    // cls_input = 33554432 elems; center_rate = 64.
    const float* cls = (const float*)d_in[0];
    const float* cr  = (const float*)d_in[1];
    if (n_in >= 2 && in_sizes[0] < in_sizes[1]) {   // defensive order check
        cls = (const float*)d_in[1];
        cr  = (const float*)d_in[0];
    }
    float* out = (float*)d_out;

    topk_scan<<<BATCH * CHUNKS, TPB>>>(cls);
    fixup<<<BATCH, TPB>>>(cls);
    select_loss<<<BATCH, TPB>>>(cr);
    finalize<<<1, 32>>>(out);
}